// round 13
// baseline (speedup 1.0000x reference)
#include <cuda_runtime.h>
#include <cstdint>

#define D_MODEL 512
#define KEY_DIM 128
#define BS_N 16
#define CTX_PER 1024
#define ARGS_PER 32
#define N_ARGS (BS_N * ARGS_PER)      /* 512  */
#define N_CTX  (BS_N * CTX_PER)       /* 16384 */
#define P_TOT  (N_ARGS * CTX_PER)     /* 524288 */

// Device globals (allocation-free scratch; device-side access only -- R3 bug).
__device__ float g_Qp[N_ARGS * D_MODEL];   // tf32-rounded
__device__ float g_qb[N_ARGS];
__device__ unsigned g_tickets = 0;         // monotonic grid barrier (replay-safe)

// ---------------------------------------------------------------------------
__device__ __forceinline__ uint32_t f2tf32(float f) {
    uint32_t r;
    asm("cvt.rna.tf32.f32 %0, %1;" : "=r"(r) : "f"(f));
    return r;
}
__device__ __forceinline__ uint32_t bits2tf32(uint32_t b) {
    return f2tf32(__uint_as_float(b));
}

__device__ __forceinline__ void mma_tf32(float (&d)[4], const uint32_t (&a)[4],
                                         uint32_t b0, uint32_t b1) {
    asm volatile(
        "mma.sync.aligned.m16n8k8.row.col.f32.tf32.tf32.f32 "
        "{%0,%1,%2,%3}, {%4,%5,%6,%7}, {%8,%9}, {%0,%1,%2,%3};"
        : "+f"(d[0]), "+f"(d[1]), "+f"(d[2]), "+f"(d[3])
        : "r"(a[0]), "r"(a[1]), "r"(a[2]), "r"(a[3]), "r"(b0), "r"(b1));
}

__device__ __forceinline__ void ldsm_x4(uint32_t (&r)[4], uint32_t addr) {
    asm volatile(
        "ldmatrix.sync.aligned.m8n8.x4.shared.b16 {%0,%1,%2,%3}, [%4];"
        : "=r"(r[0]), "=r"(r[1]), "=r"(r[2]), "=r"(r[3]) : "r"(addr));
}

__device__ __forceinline__ uint32_t s2u(const void* p) {
    return (uint32_t)__cvta_generic_to_shared(p);
}
__device__ __forceinline__ void cp16(uint32_t smem_addr, const void* gmem) {
    asm volatile("cp.async.cg.shared.global [%0], [%1], 16;"
                 :: "r"(smem_addr), "l"(gmem));
}
__device__ __forceinline__ void cp_commit() {
    asm volatile("cp.async.commit_group;");
}
template<int N> __device__ __forceinline__ void cp_wait() {
    asm volatile("cp.async.wait_group %0;" :: "n"(N));
}

// ---------------------------------------------------------------------------
// Single fused kernel. Grid (16,16) = 256 CTAs x 128 threads, 96 KB smem
// -> 2 CTAs/SM guaranteed -> all 256 CTAs resident -> grid barrier is safe.
//
// Phase 0: issue C-tile cp.async prologue (stages 0..S-2) -- overlaps phase 1.
// Phase 1: CTA (bx,by) computes Qp[32by..+32) x cols [32bx..+32) by scalar
//          FFMA (tf32-rounded store); bx==0 CTAs compute g_qb; all CTAs fill
//          a 2048-float slice of the rows plane. threadfence + ticket barrier.
// Phase 2: logits GEMM, D[32 x 64] tile of Qp_s[32,512] @ C_s[64,512]^T + qb.
//          k64 stages (2 x k32 sub-chunks), S=4 cp.async pipeline, stage
//          slots compile-time (unrolled), LDSM b16-view frags, XOR swizzle.
// ---------------------------------------------------------------------------
__global__ __launch_bounds__(128, 2) void fused_kernel(
        const float* __restrict__ argv, const float* __restrict__ ctxv,
        const float* __restrict__ Wm,   const float* __restrict__ bv,
        float* __restrict__ out_logits, float* __restrict__ rows_out) {
    constexpr int NST = 8;                          // k64 stages (512/64)
    constexpr int S   = 4;
    constexpr uint32_t QSUB = 32 * 32 * 4;          // 4 KB per k32 sub-chunk
    constexpr uint32_t CSUB = 64 * 32 * 4;          // 8 KB
    constexpr uint32_t QSTG = 2 * QSUB;             // 8 KB per stage
    constexpr uint32_t CSTG = 2 * CSUB;             // 16 KB per stage

    __shared__ float Qs[S * 2 * 32 * 32];           // 32 KB
    __shared__ float Cs[S * 2 * 64 * 32];           // 64 KB

    const int tid  = threadIdx.x;
    const int lane = tid & 31;
    const int warp = tid >> 5;
    const int wm   = warp >> 1;
    const int wn   = warp & 1;
    const int qr   = lane >> 2;
    const int qc   = lane & 3;
    const int bx   = blockIdx.x;                    // 0..15 col tile
    const int by   = blockIdx.y;                    // 0..15 state

    const int qrow_base = by * 32;
    const int crow_base = by * CTX_PER + bx * 64;
    const int ocol_base = bx * 64;

    const uint32_t QsU = s2u(Qs);
    const uint32_t CsU = s2u(Cs);

    // ---- loader offsets
    const int lrow = tid >> 3;                      // 0..15
    const int lseg = tid & 7;
    const int lsw  = (lseg ^ (lrow & 7)) * 16;

    const float* qsrc0 = g_Qp + (size_t)(qrow_base + lrow)      * D_MODEL + lseg * 4;
    const float* qsrc1 = g_Qp + (size_t)(qrow_base + lrow + 16) * D_MODEL + lseg * 4;
    const uint32_t qoff0 = (uint32_t)(lrow * 128 + lsw);
    const uint32_t qoff1 = (uint32_t)((lrow + 16) * 128 + lsw);

    const float* csrc[4];
    uint32_t coff[4];
    #pragma unroll
    for (int j = 0; j < 4; j++) {
        int r = lrow + 16 * j;
        csrc[j] = ctxv + (size_t)(crow_base + r) * D_MODEL + lseg * 4;
        coff[j] = (uint32_t)(r * 128 + lsw);
    }

    // ---- LDSM per-k8 byte offsets (within a k32 sub-chunk)
    const int arow  = 16 * wm + (lane & 15);
    const int ahi   = lane >> 4;
    const int amask = arow & 7;
    const int browL = 32 * wn + (lane & 15);
    const int browH = browL + 16;
    const int bmask = browL & 7;
    uint32_t aoff[4], boffL[4], boffH[4];
    #pragma unroll
    for (int kk = 0; kk < 4; kk++) {
        aoff[kk]  = (uint32_t)(arow * 128 + (((kk * 2 + ahi) ^ amask) * 16));
        boffL[kk] = (uint32_t)(browL * 128 + (((kk * 2 + ahi) ^ bmask) * 16));
        boffH[kk] = (uint32_t)(browH * 128 + (((kk * 2 + ahi) ^ bmask) * 16));
    }

    // ================= Phase 0: C prologue (no Qp dependency) ==============
    #pragma unroll
    for (int s = 0; s < S - 1; s++) {
        #pragma unroll
        for (int sub = 0; sub < 2; sub++) {
            const int ks = s * 64 + sub * 32;
            #pragma unroll
            for (int j = 0; j < 4; j++)
                cp16(CsU + s * CSTG + sub * CSUB + coff[j], csrc[j] + ks);
        }
        cp_commit();
    }

    // ================= Phase 1: Qp slice + qb + rows plane =================
    {
        // Qp rows [32by..+32), cols [32bx..+32): thread = (row tid>>2, 8 cols)
        const int r  = qrow_base + (tid >> 2);
        const int d0 = bx * 32 + (tid & 3) * 8;
        const float* ap = argv + (size_t)r * KEY_DIM;
        float sum[8] = {};
        #pragma unroll 4
        for (int k4 = 0; k4 < KEY_DIM / 4; k4++) {
            float4 a = *(const float4*)(ap + 4 * k4);
            #pragma unroll
            for (int j = 0; j < 8; j++) {
                float4 w = *(const float4*)(Wm + (size_t)(d0 + j) * KEY_DIM + 4 * k4);
                sum[j] = fmaf(a.x, w.x, sum[j]);
                sum[j] = fmaf(a.y, w.y, sum[j]);
                sum[j] = fmaf(a.z, w.z, sum[j]);
                sum[j] = fmaf(a.w, w.w, sum[j]);
            }
        }
        float4 v0 = make_float4(__uint_as_float(f2tf32(sum[0])),
                                __uint_as_float(f2tf32(sum[1])),
                                __uint_as_float(f2tf32(sum[2])),
                                __uint_as_float(f2tf32(sum[3])));
        float4 v1 = make_float4(__uint_as_float(f2tf32(sum[4])),
                                __uint_as_float(f2tf32(sum[5])),
                                __uint_as_float(f2tf32(sum[6])),
                                __uint_as_float(f2tf32(sum[7])));
        *(float4*)(g_Qp + (size_t)r * D_MODEL + d0)     = v0;
        *(float4*)(g_Qp + (size_t)r * D_MODEL + d0 + 4) = v1;

        // qb on the bx==0 column of CTAs
        if (bx == 0) {
            const int seg = tid & 3;
            const float* bp = bv + seg * 32;
            const float* ap2 = ap + seg * 32;
            float s = 0.f;
            #pragma unroll
            for (int k = 0; k < 8; k++) {
                float4 a  = *(const float4*)(ap2 + 4 * k);
                float4 bb = *(const float4*)(bp + 4 * k);
                s = fmaf(a.x, bb.x, s); s = fmaf(a.y, bb.y, s);
                s = fmaf(a.z, bb.z, s); s = fmaf(a.w, bb.w, s);
            }
            s += __shfl_xor_sync(0xffffffffu, s, 1);
            s += __shfl_xor_sync(0xffffffffu, s, 2);
            if (seg == 0) g_qb[r] = s;
        }

        // rows plane: 2048 floats per CTA
        if (rows_out) {
            const int base = (by * 16 + bx) * 2048;
            float* dst = rows_out + base;
            #pragma unroll
            for (int i = 0; i < 4; i++) {
                int idx = tid * 4 + i * 512;
                float fr = (float)((base + idx) >> 10);
                *(float4*)(dst + idx) = make_float4(fr, fr, fr, fr);
            }
        }
    }

    // ---- device-wide ticket barrier (all 256 CTAs resident: 2 CTAs/SM)
    __threadfence();
    if (tid == 0) {
        unsigned t = atomicAdd(&g_tickets, 1u);
        unsigned target = (t / 256u + 1u) * 256u;
        unsigned cur;
        do {
            __nanosleep(64);
            asm volatile("ld.global.acquire.gpu.u32 %0, [%1];"
                         : "=r"(cur) : "l"(&g_tickets));
        } while (cur < target);
        __threadfence();
    }
    __syncthreads();

    // ================= Phase 2: logits GEMM ================================
    // Q prologue (stages 0..S-2) in ONE group, then drain everything.
    #pragma unroll
    for (int s = 0; s < S - 1; s++) {
        #pragma unroll
        for (int sub = 0; sub < 2; sub++) {
            const int ks = s * 64 + sub * 32;
            cp16(QsU + s * QSTG + sub * QSUB + qoff0, qsrc0 + ks);
            cp16(QsU + s * QSTG + sub * QSUB + qoff1, qsrc1 + ks);
        }
    }
    cp_commit();
    cp_wait<0>();
    __syncthreads();

    float acc[4][4] = {};

    #pragma unroll 1
    for (int it4 = 0; it4 < NST / S; it4++) {
        #pragma unroll
        for (int s = 0; s < S; s++) {
            const int st = it4 * S + s;
            cp_wait<S - 2>();          // first 2 stages already drained above
            __syncthreads();

            const uint32_t qstage = QsU + s * QSTG;
            const uint32_t cstage = CsU + s * CSTG;
            #pragma unroll
            for (int sub = 0; sub < 2; sub++) {
                const uint32_t qsub = qstage + sub * QSUB;
                const uint32_t csub = cstage + sub * CSUB;
                #pragma unroll
                for (int kk = 0; kk < 4; kk++) {
                    uint32_t a[4], bl[4], bh[4];
                    ldsm_x4(a,  qsub + aoff[kk]);
                    ldsm_x4(bl, csub + boffL[kk]);
                    ldsm_x4(bh, csub + boffH[kk]);
                    #pragma unroll
                    for (int u = 0; u < 4; u++) {
                        bl[u] = bits2tf32(bl[u]);
                        bh[u] = bits2tf32(bh[u]);
                    }
                    mma_tf32(acc[0], a, bl[0], bl[2]);
                    mma_tf32(acc[1], a, bl[1], bl[3]);
                    mma_tf32(acc[2], a, bh[0], bh[2]);
                    mma_tf32(acc[3], a, bh[1], bh[3]);
                }
            }

            if (st + S - 1 < NST) {
                const int nb = (s + S - 1) & (S - 1);   // compile-time slot
                #pragma unroll
                for (int sub = 0; sub < 2; sub++) {
                    const int ks = (st + S - 1) * 64 + sub * 32;
                    cp16(QsU + nb * QSTG + sub * QSUB + qoff0, qsrc0 + ks);
                    cp16(QsU + nb * QSTG + sub * QSUB + qoff1, qsrc1 + ks);
                    #pragma unroll
                    for (int j = 0; j < 4; j++)
                        cp16(CsU + nb * CSTG + sub * CSUB + coff[j], csrc[j] + ks);
                }
            }
            cp_commit();
        }
    }

    // ---- epilogue: warp rows [16wm,+16), cols [32wn,+32)
    #pragma unroll
    for (int nt = 0; nt < 4; nt++) {
        #pragma unroll
        for (int half = 0; half < 2; half++) {
            const int rg = qrow_base + 16 * wm + qr + half * 8;
            const int col = ocol_base + 32 * wn + nt * 8 + qc * 2;
            const size_t off = (size_t)rg * CTX_PER + col;
            const float qb = __ldcg(&g_qb[rg]);
            *(float2*)(out_logits + off) =
                make_float2(acc[nt][half * 2 + 0] + qb,
                            acc[nt][half * 2 + 1] + qb);
        }
    }
}

// ---------------------------------------------------------------------------
extern "C" void kernel_launch(void* const* d_in, const int* in_sizes, int n_in,
                              void* d_out, int out_size) {
    const float* argv = nullptr;
    const float* ctxv = nullptr;
    const float* Wm   = nullptr;
    const float* bv   = nullptr;
    int seen_65536 = 0;
    for (int i = 0; i < n_in; i++) {
        long sz = in_sizes[i];
        if (sz == (long)N_CTX * D_MODEL) {
            ctxv = (const float*)d_in[i];
        } else if (sz == (long)N_ARGS * KEY_DIM) {   // == D_MODEL*KEY_DIM too
            if (seen_65536++ == 0) argv = (const float*)d_in[i];
            else                   Wm   = (const float*)d_in[i];
        } else if (sz == KEY_DIM) {
            bv = (const float*)d_in[i];
        }
    }

    float* out        = (float*)d_out;
    float* rows_out   = nullptr;
    float* logits_out = out;
    if (out_size >= 2 * P_TOT) {        // (rows, logits) concatenated
        rows_out   = out;
        logits_out = out + P_TOT;
    }

    fused_kernel<<<dim3(16, 16), 128>>>(argv, ctxv, Wm, bv,
                                        logits_out, rows_out);
}

// round 14
// speedup vs baseline: 1.9178x; 1.9178x over previous
#include <cuda_runtime.h>
#include <cstdint>

#define D_MODEL 512
#define KEY_DIM 128
#define BS_N 16
#define CTX_PER 1024
#define ARGS_PER 32
#define N_ARGS (BS_N * ARGS_PER)      /* 512  */
#define N_CTX  (BS_N * CTX_PER)       /* 16384 */
#define P_TOT  (N_ARGS * CTX_PER)     /* 524288 */

// Scratch (allocation-free rule: device globals). Device-side access only
// (host-side reference = host shadow symbol, the R3 bug).
// g_Qp holds TF32-ROUNDED values so logits-A needs no cvt.
__device__ float g_Qp[N_ARGS * D_MODEL];
__device__ float g_qb[N_ARGS];

// ---------------------------------------------------------------------------
__device__ __forceinline__ uint32_t f2tf32(float f) {
    uint32_t r;
    asm("cvt.rna.tf32.f32 %0, %1;" : "=r"(r) : "f"(f));
    return r;
}
__device__ __forceinline__ uint32_t bits2tf32(uint32_t b) {
    return f2tf32(__uint_as_float(b));
}

__device__ __forceinline__ void mma_tf32(float (&d)[4], const uint32_t (&a)[4],
                                         uint32_t b0, uint32_t b1) {
    asm volatile(
        "mma.sync.aligned.m16n8k8.row.col.f32.tf32.tf32.f32 "
        "{%0,%1,%2,%3}, {%4,%5,%6,%7}, {%8,%9}, {%0,%1,%2,%3};"
        : "+f"(d[0]), "+f"(d[1]), "+f"(d[2]), "+f"(d[3])
        : "r"(a[0]), "r"(a[1]), "r"(a[2]), "r"(a[3]), "r"(b0), "r"(b1));
}

__device__ __forceinline__ void ldsm_x4(uint32_t (&r)[4], uint32_t addr) {
    asm volatile(
        "ldmatrix.sync.aligned.m8n8.x4.shared.b16 {%0,%1,%2,%3}, [%4];"
        : "=r"(r[0]), "=r"(r[1]), "=r"(r[2]), "=r"(r[3]) : "r"(addr));
}

__device__ __forceinline__ uint32_t s2u(const void* p) {
    return (uint32_t)__cvta_generic_to_shared(p);
}
__device__ __forceinline__ void cp16(uint32_t smem_addr, const void* gmem) {
    asm volatile("cp.async.cg.shared.global [%0], [%1], 16;"
                 :: "r"(smem_addr), "l"(gmem));
}
__device__ __forceinline__ void cp_commit() {
    asm volatile("cp.async.commit_group;");
}
template<int N> __device__ __forceinline__ void cp_wait() {
    asm volatile("cp.async.wait_group %0;" :: "n"(N));
}

// ===========================================================================
// LOGITS kernel: D[32 x 32] tile of Qp_s[32,512] @ C_s[32,512]^T + qb.
//   Grid (32,16) = 512 CTAs (~3.5 CTAs/SM), 128 threads = 4 warps as
//   2(m) x 2(n), warp tile m16 x n16. S=4 cp.async pipeline (stage = 32 k,
//   8 KB) -> 32 KB smem -> 4 CTAs/SM allowed. Compile-time stage slots,
//   LDSM b16-view frags, XOR-swizzled 128B rows. A (g_Qp) pre-rounded tf32.
// ===========================================================================
__global__ __launch_bounds__(128, 4) void logits_tc(const float* __restrict__ Cm,
                                                    float* __restrict__ out) {
    constexpr int NST = 16;                         // 512 / 32
    constexpr int S   = 4;
    constexpr uint32_t QSTG = 32 * 32 * 4;          // 4 KB
    constexpr uint32_t CSTG = 32 * 32 * 4;          // 4 KB

    __shared__ float Qs[S * 32 * 32];
    __shared__ float Cs[S * 32 * 32];

    const int tid  = threadIdx.x;
    const int lane = tid & 31;
    const int warp = tid >> 5;
    const int wm   = warp >> 1;
    const int wn   = warp & 1;
    const int qr   = lane >> 2;
    const int qc   = lane & 3;

    const int qrow_base = blockIdx.y * 32;
    const int crow_base = blockIdx.y * CTX_PER + blockIdx.x * 32;
    const int ocol_base = blockIdx.x * 32;

    const uint32_t QsU = s2u(Qs);
    const uint32_t CsU = s2u(Cs);

    // ---- loaders: 2 Q rows + 2 C rows per thread per stage
    const int lrow = tid >> 3;                      // 0..15
    const int lseg = tid & 7;
    const int lsw  = (lseg ^ (lrow & 7)) * 16;

    const float* qsrc0 = g_Qp + (size_t)(qrow_base + lrow)      * D_MODEL + lseg * 4;
    const float* qsrc1 = g_Qp + (size_t)(qrow_base + lrow + 16) * D_MODEL + lseg * 4;
    const uint32_t qoff0 = (uint32_t)(lrow * 128 + lsw);
    const uint32_t qoff1 = (uint32_t)((lrow + 16) * 128 + lsw);

    const float* csrc0 = Cm + (size_t)(crow_base + lrow)      * D_MODEL + lseg * 4;
    const float* csrc1 = Cm + (size_t)(crow_base + lrow + 16) * D_MODEL + lseg * 4;
    const uint32_t coff0 = qoff0;                   // same row/seg pattern
    const uint32_t coff1 = qoff1;

    // ---- LDSM per-kk byte offsets
    const int arow  = 16 * wm + (lane & 15);
    const int ahi   = lane >> 4;
    const int amask = arow & 7;
    const int brow  = 16 * wn + (lane & 15);
    const int bmask = brow & 7;
    uint32_t aoff[4], boff[4];
    #pragma unroll
    for (int kk = 0; kk < 4; kk++) {
        aoff[kk] = (uint32_t)(arow * 128 + (((kk * 2 + ahi) ^ amask) * 16));
        boff[kk] = (uint32_t)(brow * 128 + (((kk * 2 + ahi) ^ bmask) * 16));
    }

    float acc[2][4] = {};

    // ---- prologue
    #pragma unroll
    for (int s = 0; s < S - 1; s++) {
        cp16(QsU + s * QSTG + qoff0, qsrc0 + s * 32);
        cp16(QsU + s * QSTG + qoff1, qsrc1 + s * 32);
        cp16(CsU + s * CSTG + coff0, csrc0 + s * 32);
        cp16(CsU + s * CSTG + coff1, csrc1 + s * 32);
        cp_commit();
    }

    // ---- main loop: inner unroll x S -> compile-time stage slots
    #pragma unroll 1
    for (int itS = 0; itS < NST / S; itS++) {
        #pragma unroll
        for (int s = 0; s < S; s++) {
            const int st = itS * S + s;
            cp_wait<S - 2>();
            __syncthreads();

            const uint32_t qstage = QsU + s * QSTG;
            const uint32_t cstage = CsU + s * CSTG;
            #pragma unroll
            for (int kk = 0; kk < 4; kk++) {
                uint32_t a[4], b[4];
                ldsm_x4(a, qstage + aoff[kk]);
                ldsm_x4(b, cstage + boff[kk]);
                #pragma unroll
                for (int u = 0; u < 4; u++) b[u] = bits2tf32(b[u]);
                mma_tf32(acc[0], a, b[0], b[2]);
                mma_tf32(acc[1], a, b[1], b[3]);
            }

            if (st + S - 1 < NST) {
                const int nb = (s + S - 1) & (S - 1);
                const int ks = (st + S - 1) * 32;
                cp16(QsU + nb * QSTG + qoff0, qsrc0 + ks);
                cp16(QsU + nb * QSTG + qoff1, qsrc1 + ks);
                cp16(CsU + nb * CSTG + coff0, csrc0 + ks);
                cp16(CsU + nb * CSTG + coff1, csrc1 + ks);
            }
            cp_commit();
        }
    }

    // ---- epilogue: warp rows [16wm,+16), cols [16wn,+16)
    #pragma unroll
    for (int nt = 0; nt < 2; nt++) {
        #pragma unroll
        for (int half = 0; half < 2; half++) {
            const int rg = qrow_base + 16 * wm + qr + half * 8;
            const int col = ocol_base + 16 * wn + nt * 8 + qc * 2;
            const size_t off = (size_t)rg * CTX_PER + col;
            const float qb = g_qb[rg];
            *(float2*)(out + off) = make_float2(acc[nt][half * 2 + 0] + qb,
                                                acc[nt][half * 2 + 1] + qb);
        }
    }
}

// ===========================================================================
// QP kernel (verbatim R12 shape): D[32 x 64] of arg[32,128] @ W[64,128]^T,
// tf32-rounded into g_Qp; + qb on blockIdx.x==0; + rows plane.
//   Grid (8,16) = 128 CTAs, 128 threads = 2m x 2n warps (m16 x n32).
// ===========================================================================
__global__ __launch_bounds__(128, 4) void qp_tc(const float* __restrict__ Qm,
                                                const float* __restrict__ Cm,
                                                const float* __restrict__ bv,
                                                float* __restrict__ rows_out) {
    constexpr int NST = 4;                          // 128 / 32
    constexpr int S   = 4;
    constexpr uint32_t QSTG = 32 * 32 * 4;
    constexpr uint32_t CSTG = 64 * 32 * 4;

    __shared__ float Qs[S * 32 * 32];
    __shared__ float Cs[S * 64 * 32];

    const int tid  = threadIdx.x;
    const int lane = tid & 31;
    const int warp = tid >> 5;
    const int wm   = warp >> 1;
    const int wn   = warp & 1;
    const int qr   = lane >> 2;
    const int qc   = lane & 3;

    const int qrow_base = blockIdx.y * 32;
    const int crow_base = blockIdx.x * 64;
    const int ocol_base = blockIdx.x * 64;

    const uint32_t QsU = s2u(Qs);
    const uint32_t CsU = s2u(Cs);

    const int lrow = tid >> 3;
    const int lseg = tid & 7;
    const int lsw  = (lseg ^ (lrow & 7)) * 16;

    const float* qsrc0 = Qm + (size_t)(qrow_base + lrow)      * KEY_DIM + lseg * 4;
    const float* qsrc1 = Qm + (size_t)(qrow_base + lrow + 16) * KEY_DIM + lseg * 4;
    const uint32_t qoff0 = (uint32_t)(lrow * 128 + lsw);
    const uint32_t qoff1 = (uint32_t)((lrow + 16) * 128 + lsw);

    const float* csrc[4];
    uint32_t coff[4];
    #pragma unroll
    for (int j = 0; j < 4; j++) {
        int r = lrow + 16 * j;
        csrc[j] = Cm + (size_t)(crow_base + r) * KEY_DIM + lseg * 4;
        coff[j] = (uint32_t)(r * 128 + lsw);
    }

    const int arow  = 16 * wm + (lane & 15);
    const int ahi   = lane >> 4;
    const int amask = arow & 7;
    const int browL = 32 * wn + (lane & 15);
    const int browH = browL + 16;
    const int bmask = browL & 7;
    uint32_t aoff[4], boffL[4], boffH[4];
    #pragma unroll
    for (int kk = 0; kk < 4; kk++) {
        aoff[kk]  = (uint32_t)(arow * 128 + (((kk * 2 + ahi) ^ amask) * 16));
        boffL[kk] = (uint32_t)(browL * 128 + (((kk * 2 + ahi) ^ bmask) * 16));
        boffH[kk] = (uint32_t)(browH * 128 + (((kk * 2 + ahi) ^ bmask) * 16));
    }

    float acc[4][4] = {};

    #pragma unroll
    for (int s = 0; s < S - 1; s++) {
        cp16(QsU + s * QSTG + qoff0, qsrc0 + s * 32);
        cp16(QsU + s * QSTG + qoff1, qsrc1 + s * 32);
        #pragma unroll
        for (int j = 0; j < 4; j++)
            cp16(CsU + s * CSTG + coff[j], csrc[j] + s * 32);
        cp_commit();
    }

    #pragma unroll 1
    for (int itS = 0; itS < NST / S; itS++) {
        #pragma unroll
        for (int s = 0; s < S; s++) {
            const int st = itS * S + s;
            cp_wait<S - 2>();
            __syncthreads();

            const uint32_t qstage = QsU + s * QSTG;
            const uint32_t cstage = CsU + s * CSTG;
            #pragma unroll
            for (int kk = 0; kk < 4; kk++) {
                uint32_t a[4], bl[4], bh[4];
                ldsm_x4(a,  qstage + aoff[kk]);
                ldsm_x4(bl, cstage + boffL[kk]);
                ldsm_x4(bh, cstage + boffH[kk]);
                #pragma unroll
                for (int u = 0; u < 4; u++) {
                    a[u]  = bits2tf32(a[u]);
                    bl[u] = bits2tf32(bl[u]);
                    bh[u] = bits2tf32(bh[u]);
                }
                mma_tf32(acc[0], a, bl[0], bl[2]);
                mma_tf32(acc[1], a, bl[1], bl[3]);
                mma_tf32(acc[2], a, bh[0], bh[2]);
                mma_tf32(acc[3], a, bh[1], bh[3]);
            }

            if (st + S - 1 < NST) {
                const int nb = (s + S - 1) & (S - 1);
                const int ks = (st + S - 1) * 32;
                cp16(QsU + nb * QSTG + qoff0, qsrc0 + ks);
                cp16(QsU + nb * QSTG + qoff1, qsrc1 + ks);
                #pragma unroll
                for (int j = 0; j < 4; j++)
                    cp16(CsU + nb * CSTG + coff[j], csrc[j] + ks);
            }
            cp_commit();
        }
    }

    #pragma unroll
    for (int nt = 0; nt < 4; nt++) {
        #pragma unroll
        for (int half = 0; half < 2; half++) {
            const int rg = qrow_base + 16 * wm + qr + half * 8;
            const int col = ocol_base + 32 * wn + nt * 8 + qc * 2;
            *(float2*)(g_Qp + (size_t)rg * D_MODEL + col) =
                make_float2(__uint_as_float(f2tf32(acc[nt][half * 2 + 0])),
                            __uint_as_float(f2tf32(acc[nt][half * 2 + 1])));
        }
    }

    // rows plane: rows[p] = p >> 10, spread over 128 CTAs
    if (rows_out) {
        const int cta = blockIdx.y * gridDim.x + blockIdx.x;
        const int base = cta * 4096;
        float* dst = rows_out + base;
        #pragma unroll
        for (int i = 0; i < 8; i++) {
            int idx = tid * 4 + i * 512;
            float fr = (float)((base + idx) >> 10);
            *(float4*)(dst + idx) = make_float4(fr, fr, fr, fr);
        }
    }
    // fused qb (one column of blocks): 32 rows x 4 segs = 128 threads
    if (blockIdx.x == 0) {
        const int row = qrow_base + (tid >> 2);
        const int seg = tid & 3;
        const float* ap = Qm + (size_t)row * KEY_DIM + seg * 32;
        const float* bp = bv + seg * 32;
        float s = 0.f;
        #pragma unroll
        for (int k = 0; k < 8; k++) {
            float4 a  = *(const float4*)(ap + 4 * k);
            float4 bb = *(const float4*)(bp + 4 * k);
            s = fmaf(a.x, bb.x, s); s = fmaf(a.y, bb.y, s);
            s = fmaf(a.z, bb.z, s); s = fmaf(a.w, bb.w, s);
        }
        s += __shfl_xor_sync(0xffffffffu, s, 1);
        s += __shfl_xor_sync(0xffffffffu, s, 2);
        if (seg == 0) g_qb[row] = s;
    }
}

// ---------------------------------------------------------------------------
extern "C" void kernel_launch(void* const* d_in, const int* in_sizes, int n_in,
                              void* d_out, int out_size) {
    const float* argv = nullptr;
    const float* ctxv = nullptr;
    const float* Wm   = nullptr;
    const float* bv   = nullptr;
    int seen_65536 = 0;
    for (int i = 0; i < n_in; i++) {
        long sz = in_sizes[i];
        if (sz == (long)N_CTX * D_MODEL) {
            ctxv = (const float*)d_in[i];
        } else if (sz == (long)N_ARGS * KEY_DIM) {   // == D_MODEL*KEY_DIM too
            if (seen_65536++ == 0) argv = (const float*)d_in[i];
            else                   Wm   = (const float*)d_in[i];
        } else if (sz == KEY_DIM) {
            bv = (const float*)d_in[i];
        }
    }

    float* out        = (float*)d_out;
    float* rows_out   = nullptr;
    float* logits_out = out;
    if (out_size >= 2 * P_TOT) {        // (rows, logits) concatenated
        rows_out   = out;
        logits_out = out + P_TOT;
    }

    // Qp = arg @ W^T (+ qb + rows plane): 128 CTAs x 128 thr
    qp_tc<<<dim3(8, 16), 128>>>(argv, Wm, bv, rows_out);

    // logits: [32,1024] per state = Qp_s @ C_s^T + qb: 512 CTAs x 128 thr
    logits_tc<<<dim3(32, 16), 128>>>(ctxv, logits_out);
}

// round 15
// speedup vs baseline: 1.9469x; 1.0152x over previous
#include <cuda_runtime.h>
#include <cstdint>

#define D_MODEL 512
#define KEY_DIM 128
#define BS_N 16
#define CTX_PER 1024
#define ARGS_PER 32
#define N_ARGS (BS_N * ARGS_PER)      /* 512  */
#define N_CTX  (BS_N * CTX_PER)       /* 16384 */
#define P_TOT  (N_ARGS * CTX_PER)     /* 524288 */

// Scratch (allocation-free rule: device globals). Device-side access only
// (host-side reference = host shadow symbol, the R3 bug).
// g_Qp holds TF32-ROUNDED values so logits-A needs no cvt.
__device__ float g_Qp[N_ARGS * D_MODEL];
__device__ float g_qb[N_ARGS];

// ---------------------------------------------------------------------------
__device__ __forceinline__ uint32_t f2tf32(float f) {
    uint32_t r;
    asm("cvt.rna.tf32.f32 %0, %1;" : "=r"(r) : "f"(f));
    return r;
}
__device__ __forceinline__ uint32_t bits2tf32(uint32_t b) {
    return f2tf32(__uint_as_float(b));
}

__device__ __forceinline__ void mma_tf32(float (&d)[4], const uint32_t (&a)[4],
                                         uint32_t b0, uint32_t b1) {
    asm volatile(
        "mma.sync.aligned.m16n8k8.row.col.f32.tf32.tf32.f32 "
        "{%0,%1,%2,%3}, {%4,%5,%6,%7}, {%8,%9}, {%0,%1,%2,%3};"
        : "+f"(d[0]), "+f"(d[1]), "+f"(d[2]), "+f"(d[3])
        : "r"(a[0]), "r"(a[1]), "r"(a[2]), "r"(a[3]), "r"(b0), "r"(b1));
}

__device__ __forceinline__ void ldsm_x4(uint32_t (&r)[4], uint32_t addr) {
    asm volatile(
        "ldmatrix.sync.aligned.m8n8.x4.shared.b16 {%0,%1,%2,%3}, [%4];"
        : "=r"(r[0]), "=r"(r[1]), "=r"(r[2]), "=r"(r[3]) : "r"(addr));
}

__device__ __forceinline__ uint32_t s2u(const void* p) {
    return (uint32_t)__cvta_generic_to_shared(p);
}
// classic cp.async (qp kernel)
__device__ __forceinline__ void cp16(uint32_t smem_addr, const void* gmem) {
    asm volatile("cp.async.cg.shared.global [%0], [%1], 16;"
                 :: "r"(smem_addr), "l"(gmem));
}
__device__ __forceinline__ void cp_commit() {
    asm volatile("cp.async.commit_group;");
}
template<int N> __device__ __forceinline__ void cp_wait() {
    asm volatile("cp.async.wait_group %0;" :: "n"(N));
}
// bulk copy via TMA engine (no tensormap; contiguous bytes) + mbarrier
__device__ __forceinline__ void cp_bulk(uint32_t dst, const void* src,
                                        uint32_t bytes, uint32_t mbar) {
    asm volatile(
        "cp.async.bulk.shared::cta.global.mbarrier::complete_tx::bytes "
        "[%0], [%1], %2, [%3];"
        :: "r"(dst), "l"(src), "r"(bytes), "r"(mbar) : "memory");
}
#define MBARRIER_INIT(addr, cnt) \
    asm volatile("mbarrier.init.shared.b64 [%0], %1;" \
                 :: "r"((uint32_t)(addr)), "r"((uint32_t)(cnt)) : "memory")
#define MBARRIER_EXPECT_TX(addr, tx) \
    asm volatile("mbarrier.arrive.expect_tx.shared.b64 _, [%0], %1;" \
                 :: "r"((uint32_t)(addr)), "r"((uint32_t)(tx)) : "memory")
#define MBARRIER_WAIT_PARITY(addr, ph) do {                                  \
    asm volatile(                                                            \
        "{\n\t.reg .pred P1;\n\t"                                            \
        "WAIT_LOOP_%=:\n\t"                                                  \
        "mbarrier.try_wait.parity.acquire.cta.shared::cta.b64 P1, [%0], %1, 0x989680;\n\t" \
        "@P1 bra.uni WAIT_DONE_%=;\n\t"                                      \
        "bra.uni WAIT_LOOP_%=;\n\t"                                          \
        "WAIT_DONE_%=:\n\t}"                                                 \
        :: "r"((uint32_t)(addr)), "r"((uint32_t)(ph)) : "memory");           \
} while (0)

// ===========================================================================
// LOGITS kernel (bulk-row streaming):
//   CTA = (state by, 64-C-row block bx). 128 thr = 4 warps: wm=warp&1 (m16
//   half), wk=warp>>1 (K half, 256 each).
//   Phase A: 32 x 2KB bulk loads of Q_s rows into smem (rows padded to 2064B
//     -> bank-spread, LDSM conflict-free), extract ALL A fragments to regs
//     (32 LDSM.x4 = 128 regs/warp; g_Qp pre-rounded tf32 -> no cvt).
//   Phase B: same smem becomes a 2-deep ring of 16-row C stages (16 x 2KB
//     bulks each, full-K rows). Per stage: 32 k8-steps of B-LDSM.x4 + 4 cvt
//     + 2 MMA per warp, k-reduce via scratch, store D[32x16] + qb.
// ===========================================================================
#define ROWB 2064                       /* 2048 + 16B pad */
#define CB0  0
#define CB1  (16 * ROWB)
#define SCR  (32 * ROWB)                /* 2KB reduce scratch */
#define MB_Q  (SCR + 2048)
#define MB_C0 (MB_Q + 8)
#define MB_C1 (MB_C0 + 8)
#define SMEM_TOTAL (MB_C1 + 8 + 40)

__global__ __launch_bounds__(128) void logits_bulk(const float* __restrict__ Cm,
                                                   float* __restrict__ out) {
    extern __shared__ __align__(128) char smem[];
    const uint32_t base = s2u(smem);

    const int tid  = threadIdx.x;
    const int lane = tid & 31;
    const int warp = tid >> 5;
    const int wm   = warp & 1;           // m16 half
    const int wk   = warp >> 1;          // K half (0: k<256, 1: k>=256)
    const int qr   = lane >> 2;
    const int qc   = lane & 3;
    const int by   = blockIdx.y;         // state
    const int bx   = blockIdx.x;         // 64-row C block

    if (tid == 0) {
        MBARRIER_INIT(base + MB_Q, 1);
        MBARRIER_INIT(base + MB_C0, 1);
        MBARRIER_INIT(base + MB_C1, 1);
    }
    __syncthreads();

    // ---- Phase A: Q load + A-fragment extraction -------------------------
    const float* qsrc = g_Qp + (size_t)(by * 32) * D_MODEL;
    if (tid == 0) {
        MBARRIER_EXPECT_TX(base + MB_Q, 32 * 2048);
        #pragma unroll
        for (int r = 0; r < 32; r++)
            cp_bulk(base + r * ROWB, qsrc + r * D_MODEL, 2048, base + MB_Q);
    }
    MBARRIER_WAIT_PARITY(base + MB_Q, 0);

    uint32_t af[32][4];                  // A frags, statically indexed
    {
        const uint32_t a_addr = base + (wm * 16 + (lane & 15)) * ROWB
                              + (wk * 256 + (lane >> 4) * 4) * 4;
        #pragma unroll
        for (int kk = 0; kk < 32; kk++)
            ldsm_x4(af[kk], a_addr + kk * 32);
    }
    __syncthreads();                     // Q region now free for C stages

    // ---- Phase B: C streaming --------------------------------------------
    const float* csrc = Cm + (size_t)(by * CTX_PER + bx * 64) * D_MODEL;
    if (tid == 0) {
        MBARRIER_EXPECT_TX(base + MB_C0, 16 * 2048);
        #pragma unroll
        for (int r = 0; r < 16; r++)
            cp_bulk(base + CB0 + r * ROWB, csrc + r * D_MODEL, 2048, base + MB_C0);
        MBARRIER_EXPECT_TX(base + MB_C1, 16 * 2048);
        #pragma unroll
        for (int r = 0; r < 16; r++)
            cp_bulk(base + CB1 + r * ROWB, csrc + (16 + r) * D_MODEL, 2048, base + MB_C1);
    }

    const uint32_t b_lane = ((lane & 15)) * ROWB + ((lane >> 4) * 4 + wk * 256) * 4;
    float* scr = (float*)(smem + SCR) + (wm * 32 + lane) * 8;

    auto stage = [&](uint32_t bufbase, uint32_t mbar, int phase, int st) {
        MBARRIER_WAIT_PARITY(base + mbar, phase);
        float acc[2][4] = {};
        const uint32_t baddr = base + bufbase + b_lane;
        #pragma unroll
        for (int kk = 0; kk < 32; kk++) {
            uint32_t b[4];
            ldsm_x4(b, baddr + kk * 32);
            #pragma unroll
            for (int u = 0; u < 4; u++) b[u] = bits2tf32(b[u]);
            mma_tf32(acc[0], af[kk], b[0], b[2]);   // stage rows 0-7
            mma_tf32(acc[1], af[kk], b[1], b[3]);   // stage rows 8-15
        }
        // k-reduce: wk==1 writes, wk==0 adds + stores
        if (wk == 1) {
            *(float4*)(scr + 0) = make_float4(acc[0][0], acc[0][1], acc[0][2], acc[0][3]);
            *(float4*)(scr + 4) = make_float4(acc[1][0], acc[1][1], acc[1][2], acc[1][3]);
        }
        __syncthreads();
        if (wk == 0) {
            float4 p0 = *(const float4*)(scr + 0);
            float4 p1 = *(const float4*)(scr + 4);
            acc[0][0] += p0.x; acc[0][1] += p0.y; acc[0][2] += p0.z; acc[0][3] += p0.w;
            acc[1][0] += p1.x; acc[1][1] += p1.y; acc[1][2] += p1.z; acc[1][3] += p1.w;
            #pragma unroll
            for (int nt = 0; nt < 2; nt++) {
                #pragma unroll
                for (int half = 0; half < 2; half++) {
                    const int rg = by * 32 + wm * 16 + qr + half * 8;
                    const int col = bx * 64 + st * 16 + nt * 8 + qc * 2;
                    const float qb = g_qb[rg];
                    *(float2*)(out + (size_t)rg * CTX_PER + col) =
                        make_float2(acc[nt][half * 2 + 0] + qb,
                                    acc[nt][half * 2 + 1] + qb);
                }
            }
        }
        __syncthreads();                 // buffer + scratch free
    };

    stage(CB0, MB_C0, 0, 0);
    if (tid == 0) {                      // C2 -> buf0
        MBARRIER_EXPECT_TX(base + MB_C0, 16 * 2048);
        #pragma unroll
        for (int r = 0; r < 16; r++)
            cp_bulk(base + CB0 + r * ROWB, csrc + (32 + r) * D_MODEL, 2048, base + MB_C0);
    }
    stage(CB1, MB_C1, 0, 1);
    if (tid == 0) {                      // C3 -> buf1
        MBARRIER_EXPECT_TX(base + MB_C1, 16 * 2048);
        #pragma unroll
        for (int r = 0; r < 16; r++)
            cp_bulk(base + CB1 + r * ROWB, csrc + (48 + r) * D_MODEL, 2048, base + MB_C1);
    }
    stage(CB0, MB_C0, 1, 2);
    stage(CB1, MB_C1, 1, 3);
}

// ===========================================================================
// QP kernel (proven R12/R14 version): g_Qp = tf32(arg @ W^T), + qb, + rows.
// ===========================================================================
__global__ __launch_bounds__(128, 4) void qp_tc(const float* __restrict__ Qm,
                                                const float* __restrict__ Cm,
                                                const float* __restrict__ bv,
                                                float* __restrict__ rows_out) {
    constexpr int NST = 4;
    constexpr int S   = 4;
    constexpr uint32_t QSTG = 32 * 32 * 4;
    constexpr uint32_t CSTG = 64 * 32 * 4;

    __shared__ float Qs[S * 32 * 32];
    __shared__ float Cs[S * 64 * 32];

    const int tid  = threadIdx.x;
    const int lane = tid & 31;
    const int warp = tid >> 5;
    const int wm   = warp >> 1;
    const int wn   = warp & 1;
    const int qr   = lane >> 2;
    const int qc   = lane & 3;

    const int qrow_base = blockIdx.y * 32;
    const int crow_base = blockIdx.x * 64;
    const int ocol_base = blockIdx.x * 64;

    const uint32_t QsU = s2u(Qs);
    const uint32_t CsU = s2u(Cs);

    const int lrow = tid >> 3;
    const int lseg = tid & 7;
    const int lsw  = (lseg ^ (lrow & 7)) * 16;

    const float* qsrc0 = Qm + (size_t)(qrow_base + lrow)      * KEY_DIM + lseg * 4;
    const float* qsrc1 = Qm + (size_t)(qrow_base + lrow + 16) * KEY_DIM + lseg * 4;
    const uint32_t qoff0 = (uint32_t)(lrow * 128 + lsw);
    const uint32_t qoff1 = (uint32_t)((lrow + 16) * 128 + lsw);

    const float* csrc[4];
    uint32_t coff[4];
    #pragma unroll
    for (int j = 0; j < 4; j++) {
        int r = lrow + 16 * j;
        csrc[j] = Cm + (size_t)(crow_base + r) * KEY_DIM + lseg * 4;
        coff[j] = (uint32_t)(r * 128 + lsw);
    }

    const int arow  = 16 * wm + (lane & 15);
    const int ahi   = lane >> 4;
    const int amask = arow & 7;
    const int browL = 32 * wn + (lane & 15);
    const int browH = browL + 16;
    const int bmask = browL & 7;
    uint32_t aoff[4], boffL[4], boffH[4];
    #pragma unroll
    for (int kk = 0; kk < 4; kk++) {
        aoff[kk]  = (uint32_t)(arow * 128 + (((kk * 2 + ahi) ^ amask) * 16));
        boffL[kk] = (uint32_t)(browL * 128 + (((kk * 2 + ahi) ^ bmask) * 16));
        boffH[kk] = (uint32_t)(browH * 128 + (((kk * 2 + ahi) ^ bmask) * 16));
    }

    float acc[4][4] = {};

    #pragma unroll
    for (int s = 0; s < S - 1; s++) {
        cp16(QsU + s * QSTG + qoff0, qsrc0 + s * 32);
        cp16(QsU + s * QSTG + qoff1, qsrc1 + s * 32);
        #pragma unroll
        for (int j = 0; j < 4; j++)
            cp16(CsU + s * CSTG + coff[j], csrc[j] + s * 32);
        cp_commit();
    }

    #pragma unroll 1
    for (int itS = 0; itS < NST / S; itS++) {
        #pragma unroll
        for (int s = 0; s < S; s++) {
            const int st = itS * S + s;
            cp_wait<S - 2>();
            __syncthreads();

            const uint32_t qstage = QsU + s * QSTG;
            const uint32_t cstage = CsU + s * CSTG;
            #pragma unroll
            for (int kk = 0; kk < 4; kk++) {
                uint32_t a[4], bl[4], bh[4];
                ldsm_x4(a,  qstage + aoff[kk]);
                ldsm_x4(bl, cstage + boffL[kk]);
                ldsm_x4(bh, cstage + boffH[kk]);
                #pragma unroll
                for (int u = 0; u < 4; u++) {
                    a[u]  = bits2tf32(a[u]);
                    bl[u] = bits2tf32(bl[u]);
                    bh[u] = bits2tf32(bh[u]);
                }
                mma_tf32(acc[0], a, bl[0], bl[2]);
                mma_tf32(acc[1], a, bl[1], bl[3]);
                mma_tf32(acc[2], a, bh[0], bh[2]);
                mma_tf32(acc[3], a, bh[1], bh[3]);
            }

            if (st + S - 1 < NST) {
                const int nb = (s + S - 1) & (S - 1);
                const int ks = (st + S - 1) * 32;
                cp16(QsU + nb * QSTG + qoff0, qsrc0 + ks);
                cp16(QsU + nb * QSTG + qoff1, qsrc1 + ks);
                #pragma unroll
                for (int j = 0; j < 4; j++)
                    cp16(CsU + nb * CSTG + coff[j], csrc[j] + ks);
            }
            cp_commit();
        }
    }

    #pragma unroll
    for (int nt = 0; nt < 4; nt++) {
        #pragma unroll
        for (int half = 0; half < 2; half++) {
            const int rg = qrow_base + 16 * wm + qr + half * 8;
            const int col = ocol_base + 32 * wn + nt * 8 + qc * 2;
            *(float2*)(g_Qp + (size_t)rg * D_MODEL + col) =
                make_float2(__uint_as_float(f2tf32(acc[nt][half * 2 + 0])),
                            __uint_as_float(f2tf32(acc[nt][half * 2 + 1])));
        }
    }

    if (rows_out) {
        const int cta = blockIdx.y * gridDim.x + blockIdx.x;
        const int base = cta * 4096;
        float* dst = rows_out + base;
        #pragma unroll
        for (int i = 0; i < 8; i++) {
            int idx = tid * 4 + i * 512;
            float fr = (float)((base + idx) >> 10);
            *(float4*)(dst + idx) = make_float4(fr, fr, fr, fr);
        }
    }
    if (blockIdx.x == 0) {
        const int row = qrow_base + (tid >> 2);
        const int seg = tid & 3;
        const float* ap = Qm + (size_t)row * KEY_DIM + seg * 32;
        const float* bp = bv + seg * 32;
        float s = 0.f;
        #pragma unroll
        for (int k = 0; k < 8; k++) {
            float4 a  = *(const float4*)(ap + 4 * k);
            float4 bb = *(const float4*)(bp + 4 * k);
            s = fmaf(a.x, bb.x, s); s = fmaf(a.y, bb.y, s);
            s = fmaf(a.z, bb.z, s); s = fmaf(a.w, bb.w, s);
        }
        s += __shfl_xor_sync(0xffffffffu, s, 1);
        s += __shfl_xor_sync(0xffffffffu, s, 2);
        if (seg == 0) g_qb[row] = s;
    }
}

// ---------------------------------------------------------------------------
extern "C" void kernel_launch(void* const* d_in, const int* in_sizes, int n_in,
                              void* d_out, int out_size) {
    const float* argv = nullptr;
    const float* ctxv = nullptr;
    const float* Wm   = nullptr;
    const float* bv   = nullptr;
    int seen_65536 = 0;
    for (int i = 0; i < n_in; i++) {
        long sz = in_sizes[i];
        if (sz == (long)N_CTX * D_MODEL) {
            ctxv = (const float*)d_in[i];
        } else if (sz == (long)N_ARGS * KEY_DIM) {   // == D_MODEL*KEY_DIM too
            if (seen_65536++ == 0) argv = (const float*)d_in[i];
            else                   Wm   = (const float*)d_in[i];
        } else if (sz == KEY_DIM) {
            bv = (const float*)d_in[i];
        }
    }

    float* out        = (float*)d_out;
    float* rows_out   = nullptr;
    float* logits_out = out;
    if (out_size >= 2 * P_TOT) {        // (rows, logits) concatenated
        rows_out   = out;
        logits_out = out + P_TOT;
    }

    cudaFuncSetAttribute(logits_bulk,
                         cudaFuncAttributeMaxDynamicSharedMemorySize, SMEM_TOTAL);

    // Qp = arg @ W^T (+ qb + rows plane): 128 CTAs x 128 thr
    qp_tc<<<dim3(8, 16), 128>>>(argv, Wm, bv, rows_out);

    // logits: 256 CTAs x 128 thr, bulk-row streaming, 68KB dynamic smem
    logits_bulk<<<dim3(16, 16), 128, SMEM_TOTAL>>>(ctxv, logits_out);
}

// round 16
// speedup vs baseline: 2.2160x; 1.1382x over previous
#include <cuda_runtime.h>
#include <cstdint>

#define D_MODEL 512
#define KEY_DIM 128
#define BS_N 16
#define CTX_PER 1024
#define ARGS_PER 32
#define N_ARGS (BS_N * ARGS_PER)      /* 512  */
#define N_CTX  (BS_N * CTX_PER)       /* 16384 */
#define P_TOT  (N_ARGS * CTX_PER)     /* 524288 */

// Scratch (allocation-free rule: device globals). Device-side access only
// (host-side reference = host shadow symbol, the R3 bug).
// g_Qp holds TF32-ROUNDED values so logits-A needs no cvt.
__device__ float g_Qp[N_ARGS * D_MODEL];
__device__ float g_qb[N_ARGS];

// ---------------------------------------------------------------------------
__device__ __forceinline__ uint32_t f2tf32(float f) {
    uint32_t r;
    asm("cvt.rna.tf32.f32 %0, %1;" : "=r"(r) : "f"(f));
    return r;
}
__device__ __forceinline__ uint32_t bits2tf32(uint32_t b) {
    return f2tf32(__uint_as_float(b));
}

__device__ __forceinline__ void mma_tf32(float (&d)[4], const uint32_t (&a)[4],
                                         uint32_t b0, uint32_t b1) {
    asm volatile(
        "mma.sync.aligned.m16n8k8.row.col.f32.tf32.tf32.f32 "
        "{%0,%1,%2,%3}, {%4,%5,%6,%7}, {%8,%9}, {%0,%1,%2,%3};"
        : "+f"(d[0]), "+f"(d[1]), "+f"(d[2]), "+f"(d[3])
        : "r"(a[0]), "r"(a[1]), "r"(a[2]), "r"(a[3]), "r"(b0), "r"(b1));
}

__device__ __forceinline__ void ldsm_x4(uint32_t (&r)[4], uint32_t addr) {
    asm volatile(
        "ldmatrix.sync.aligned.m8n8.x4.shared.b16 {%0,%1,%2,%3}, [%4];"
        : "=r"(r[0]), "=r"(r[1]), "=r"(r[2]), "=r"(r[3]) : "r"(addr));
}

__device__ __forceinline__ uint32_t s2u(const void* p) {
    return (uint32_t)__cvta_generic_to_shared(p);
}
__device__ __forceinline__ void cp16(uint32_t smem_addr, const void* gmem) {
    asm volatile("cp.async.cg.shared.global [%0], [%1], 16;"
                 :: "r"(smem_addr), "l"(gmem));
}
__device__ __forceinline__ void cp_commit() {
    asm volatile("cp.async.commit_group;");
}
template<int N> __device__ __forceinline__ void cp_wait() {
    asm volatile("cp.async.wait_group %0;" :: "n"(N));
}
// PDL controls
__device__ __forceinline__ void pdl_trigger() {
    asm volatile("griddepcontrol.launch_dependents;");
}
__device__ __forceinline__ void pdl_wait() {
    asm volatile("griddepcontrol.wait;" ::: "memory");
}

// ===========================================================================
// LOGITS kernel (R12-proven shape + PDL split prologue):
//   D[32 x 64] tile of Qp_s[32,512] @ C_s[64,512]^T + qb.
//   Grid (16,16), 128 thr = 2m x 2n warps (warp m16 x n32), S=4 cp.async
//   pipeline (stage = 32 k), compile-time stage slots, LDSM b16-view frags,
//   XOR-swizzled 128B rows.
//   Prologue: C stages 0..2 (3 groups, NO Qp dependency) -> griddepcontrol.wait
//   (qp kernel complete) -> Q stages 0..2 (1 group) -> drain -> steady loop.
// ===========================================================================
__global__ __launch_bounds__(128, 4) void logits_tc(const float* __restrict__ Cm,
                                                    float* __restrict__ out) {
    constexpr int NST = 16;                         // 512 / 32
    constexpr int S   = 4;
    constexpr uint32_t QSTG = 32 * 32 * 4;          // 4 KB
    constexpr uint32_t CSTG = 64 * 32 * 4;          // 8 KB

    __shared__ float Qs[S * 32 * 32];               // 16 KB
    __shared__ float Cs[S * 64 * 32];               // 32 KB

    const int tid  = threadIdx.x;
    const int lane = tid & 31;
    const int warp = tid >> 5;
    const int wm   = warp >> 1;
    const int wn   = warp & 1;
    const int qr   = lane >> 2;
    const int qc   = lane & 3;

    const int qrow_base = blockIdx.y * 32;
    const int crow_base = blockIdx.y * CTX_PER + blockIdx.x * 64;
    const int ocol_base = blockIdx.x * 64;

    const uint32_t QsU = s2u(Qs);
    const uint32_t CsU = s2u(Cs);

    // ---- loader offsets
    const int lrow = tid >> 3;                      // 0..15
    const int lseg = tid & 7;
    const int lsw  = (lseg ^ (lrow & 7)) * 16;

    const float* qsrc0 = g_Qp + (size_t)(qrow_base + lrow)      * D_MODEL + lseg * 4;
    const float* qsrc1 = g_Qp + (size_t)(qrow_base + lrow + 16) * D_MODEL + lseg * 4;
    const uint32_t qoff0 = (uint32_t)(lrow * 128 + lsw);
    const uint32_t qoff1 = (uint32_t)((lrow + 16) * 128 + lsw);

    const float* csrc[4];
    uint32_t coff[4];
    #pragma unroll
    for (int j = 0; j < 4; j++) {
        int r = lrow + 16 * j;                      // 0..63
        csrc[j] = Cm + (size_t)(crow_base + r) * D_MODEL + lseg * 4;
        coff[j] = (uint32_t)(r * 128 + lsw);
    }

    // ---- LDSM per-kk byte offsets
    const int arow  = 16 * wm + (lane & 15);
    const int ahi   = lane >> 4;
    const int amask = arow & 7;
    const int browL = 32 * wn + (lane & 15);
    const int browH = browL + 16;
    const int bmask = browL & 7;
    uint32_t aoff[4], boffL[4], boffH[4];
    #pragma unroll
    for (int kk = 0; kk < 4; kk++) {
        aoff[kk]  = (uint32_t)(arow * 128 + (((kk * 2 + ahi) ^ amask) * 16));
        boffL[kk] = (uint32_t)(browL * 128 + (((kk * 2 + ahi) ^ bmask) * 16));
        boffH[kk] = (uint32_t)(browH * 128 + (((kk * 2 + ahi) ^ bmask) * 16));
    }

    float acc[4][4] = {};

    // ---- prologue part 1: C stages 0..S-2 (independent of qp's output)
    #pragma unroll
    for (int s = 0; s < S - 1; s++) {
        #pragma unroll
        for (int j = 0; j < 4; j++)
            cp16(CsU + s * CSTG + coff[j], csrc[j] + s * 32);
        cp_commit();
    }

    // ---- wait for qp kernel completion (g_Qp / g_qb now valid)
    pdl_wait();

    // ---- prologue part 2: Q stages 0..S-2 (one group), then drain all
    #pragma unroll
    for (int s = 0; s < S - 1; s++) {
        cp16(QsU + s * QSTG + qoff0, qsrc0 + s * 32);
        cp16(QsU + s * QSTG + qoff1, qsrc1 + s * 32);
    }
    cp_commit();
    cp_wait<0>();
    __syncthreads();

    // ---- main loop: inner unroll x S -> compile-time stage slots
    #pragma unroll 1
    for (int itS = 0; itS < NST / S; itS++) {
        #pragma unroll
        for (int s = 0; s < S; s++) {
            const int st = itS * S + s;
            cp_wait<S - 2>();
            __syncthreads();

            const uint32_t qstage = QsU + s * QSTG;
            const uint32_t cstage = CsU + s * CSTG;
            #pragma unroll
            for (int kk = 0; kk < 4; kk++) {
                uint32_t a[4], bl[4], bh[4];
                ldsm_x4(a,  qstage + aoff[kk]);
                ldsm_x4(bl, cstage + boffL[kk]);
                ldsm_x4(bh, cstage + boffH[kk]);
                #pragma unroll
                for (int u = 0; u < 4; u++) {
                    bl[u] = bits2tf32(bl[u]);
                    bh[u] = bits2tf32(bh[u]);
                }
                mma_tf32(acc[0], a, bl[0], bl[2]);
                mma_tf32(acc[1], a, bl[1], bl[3]);
                mma_tf32(acc[2], a, bh[0], bh[2]);
                mma_tf32(acc[3], a, bh[1], bh[3]);
            }

            if (st + S - 1 < NST) {
                const int nb = (s + S - 1) & (S - 1);   // compile-time slot
                const int ks = (st + S - 1) * 32;
                cp16(QsU + nb * QSTG + qoff0, qsrc0 + ks);
                cp16(QsU + nb * QSTG + qoff1, qsrc1 + ks);
                #pragma unroll
                for (int j = 0; j < 4; j++)
                    cp16(CsU + nb * CSTG + coff[j], csrc[j] + ks);
            }
            cp_commit();
        }
    }

    // ---- epilogue: warp rows [16wm,+16), cols [32wn,+32)
    #pragma unroll
    for (int nt = 0; nt < 4; nt++) {
        #pragma unroll
        for (int half = 0; half < 2; half++) {
            const int rg = qrow_base + 16 * wm + qr + half * 8;
            const int col = ocol_base + 32 * wn + nt * 8 + qc * 2;
            const size_t off = (size_t)rg * CTX_PER + col;
            const float qb = g_qb[rg];
            *(float2*)(out + off) = make_float2(acc[nt][half * 2 + 0] + qb,
                                                acc[nt][half * 2 + 1] + qb);
        }
    }
}

// ===========================================================================
// QP kernel (proven R12 version + PDL trigger): g_Qp = tf32(arg @ W^T),
// + qb on blockIdx.x==0, + rows plane. Grid (8,16), 128 thr.
// ===========================================================================
__global__ __launch_bounds__(128, 4) void qp_tc(const float* __restrict__ Qm,
                                                const float* __restrict__ Cm,
                                                const float* __restrict__ bv,
                                                float* __restrict__ rows_out) {
    constexpr int NST = 4;
    constexpr int S   = 4;
    constexpr uint32_t QSTG = 32 * 32 * 4;
    constexpr uint32_t CSTG = 64 * 32 * 4;

    __shared__ float Qs[S * 32 * 32];
    __shared__ float Cs[S * 64 * 32];

    pdl_trigger();                      // let logits_tc start its C prologue

    const int tid  = threadIdx.x;
    const int lane = tid & 31;
    const int warp = tid >> 5;
    const int wm   = warp >> 1;
    const int wn   = warp & 1;
    const int qr   = lane >> 2;
    const int qc   = lane & 3;

    const int qrow_base = blockIdx.y * 32;
    const int crow_base = blockIdx.x * 64;
    const int ocol_base = blockIdx.x * 64;

    const uint32_t QsU = s2u(Qs);
    const uint32_t CsU = s2u(Cs);

    const int lrow = tid >> 3;
    const int lseg = tid & 7;
    const int lsw  = (lseg ^ (lrow & 7)) * 16;

    const float* qsrc0 = Qm + (size_t)(qrow_base + lrow)      * KEY_DIM + lseg * 4;
    const float* qsrc1 = Qm + (size_t)(qrow_base + lrow + 16) * KEY_DIM + lseg * 4;
    const uint32_t qoff0 = (uint32_t)(lrow * 128 + lsw);
    const uint32_t qoff1 = (uint32_t)((lrow + 16) * 128 + lsw);

    const float* csrc[4];
    uint32_t coff[4];
    #pragma unroll
    for (int j = 0; j < 4; j++) {
        int r = lrow + 16 * j;
        csrc[j] = Cm + (size_t)(crow_base + r) * KEY_DIM + lseg * 4;
        coff[j] = (uint32_t)(r * 128 + lsw);
    }

    const int arow  = 16 * wm + (lane & 15);
    const int ahi   = lane >> 4;
    const int amask = arow & 7;
    const int browL = 32 * wn + (lane & 15);
    const int browH = browL + 16;
    const int bmask = browL & 7;
    uint32_t aoff[4], boffL[4], boffH[4];
    #pragma unroll
    for (int kk = 0; kk < 4; kk++) {
        aoff[kk]  = (uint32_t)(arow * 128 + (((kk * 2 + ahi) ^ amask) * 16));
        boffL[kk] = (uint32_t)(browL * 128 + (((kk * 2 + ahi) ^ bmask) * 16));
        boffH[kk] = (uint32_t)(browH * 128 + (((kk * 2 + ahi) ^ bmask) * 16));
    }

    float acc[4][4] = {};

    #pragma unroll
    for (int s = 0; s < S - 1; s++) {
        cp16(QsU + s * QSTG + qoff0, qsrc0 + s * 32);
        cp16(QsU + s * QSTG + qoff1, qsrc1 + s * 32);
        #pragma unroll
        for (int j = 0; j < 4; j++)
            cp16(CsU + s * CSTG + coff[j], csrc[j] + s * 32);
        cp_commit();
    }

    #pragma unroll 1
    for (int itS = 0; itS < NST / S; itS++) {
        #pragma unroll
        for (int s = 0; s < S; s++) {
            const int st = itS * S + s;
            cp_wait<S - 2>();
            __syncthreads();

            const uint32_t qstage = QsU + s * QSTG;
            const uint32_t cstage = CsU + s * CSTG;
            #pragma unroll
            for (int kk = 0; kk < 4; kk++) {
                uint32_t a[4], bl[4], bh[4];
                ldsm_x4(a,  qstage + aoff[kk]);
                ldsm_x4(bl, cstage + boffL[kk]);
                ldsm_x4(bh, cstage + boffH[kk]);
                #pragma unroll
                for (int u = 0; u < 4; u++) {
                    a[u]  = bits2tf32(a[u]);
                    bl[u] = bits2tf32(bl[u]);
                    bh[u] = bits2tf32(bh[u]);
                }
                mma_tf32(acc[0], a, bl[0], bl[2]);
                mma_tf32(acc[1], a, bl[1], bl[3]);
                mma_tf32(acc[2], a, bh[0], bh[2]);
                mma_tf32(acc[3], a, bh[1], bh[3]);
            }

            if (st + S - 1 < NST) {
                const int nb = (s + S - 1) & (S - 1);
                const int ks = (st + S - 1) * 32;
                cp16(QsU + nb * QSTG + qoff0, qsrc0 + ks);
                cp16(QsU + nb * QSTG + qoff1, qsrc1 + ks);
                #pragma unroll
                for (int j = 0; j < 4; j++)
                    cp16(CsU + nb * CSTG + coff[j], csrc[j] + ks);
            }
            cp_commit();
        }
    }

    #pragma unroll
    for (int nt = 0; nt < 4; nt++) {
        #pragma unroll
        for (int half = 0; half < 2; half++) {
            const int rg = qrow_base + 16 * wm + qr + half * 8;
            const int col = ocol_base + 32 * wn + nt * 8 + qc * 2;
            *(float2*)(g_Qp + (size_t)rg * D_MODEL + col) =
                make_float2(__uint_as_float(f2tf32(acc[nt][half * 2 + 0])),
                            __uint_as_float(f2tf32(acc[nt][half * 2 + 1])));
        }
    }

    if (rows_out) {
        const int cta = blockIdx.y * gridDim.x + blockIdx.x;
        const int base = cta * 4096;
        float* dst = rows_out + base;
        #pragma unroll
        for (int i = 0; i < 8; i++) {
            int idx = tid * 4 + i * 512;
            float fr = (float)((base + idx) >> 10);
            *(float4*)(dst + idx) = make_float4(fr, fr, fr, fr);
        }
    }
    if (blockIdx.x == 0) {
        const int row = qrow_base + (tid >> 2);
        const int seg = tid & 3;
        const float* ap = Qm + (size_t)row * KEY_DIM + seg * 32;
        const float* bp = bv + seg * 32;
        float s = 0.f;
        #pragma unroll
        for (int k = 0; k < 8; k++) {
            float4 a  = *(const float4*)(ap + 4 * k);
            float4 bb = *(const float4*)(bp + 4 * k);
            s = fmaf(a.x, bb.x, s); s = fmaf(a.y, bb.y, s);
            s = fmaf(a.z, bb.z, s); s = fmaf(a.w, bb.w, s);
        }
        s += __shfl_xor_sync(0xffffffffu, s, 1);
        s += __shfl_xor_sync(0xffffffffu, s, 2);
        if (seg == 0) g_qb[row] = s;
    }
}

// ---------------------------------------------------------------------------
extern "C" void kernel_launch(void* const* d_in, const int* in_sizes, int n_in,
                              void* d_out, int out_size) {
    const float* argv = nullptr;
    const float* ctxv = nullptr;
    const float* Wm   = nullptr;
    const float* bv   = nullptr;
    int seen_65536 = 0;
    for (int i = 0; i < n_in; i++) {
        long sz = in_sizes[i];
        if (sz == (long)N_CTX * D_MODEL) {
            ctxv = (const float*)d_in[i];
        } else if (sz == (long)N_ARGS * KEY_DIM) {   // == D_MODEL*KEY_DIM too
            if (seen_65536++ == 0) argv = (const float*)d_in[i];
            else                   Wm   = (const float*)d_in[i];
        } else if (sz == KEY_DIM) {
            bv = (const float*)d_in[i];
        }
    }

    float* out        = (float*)d_out;
    float* rows_out   = nullptr;
    float* logits_out = out;
    if (out_size >= 2 * P_TOT) {        // (rows, logits) concatenated
        rows_out   = out;
        logits_out = out + P_TOT;
    }

    // Primary: Qp = arg @ W^T (+ qb + rows plane)
    qp_tc<<<dim3(8, 16), 128>>>(argv, Wm, bv, rows_out);

    // Secondary (PDL): logits overlaps its C prologue with qp's execution.
    cudaLaunchConfig_t cfg = {};
    cfg.gridDim  = dim3(16, 16);
    cfg.blockDim = dim3(128);
    cfg.dynamicSmemBytes = 0;
    cfg.stream = 0;
    cudaLaunchAttribute attrs[1];
    attrs[0].id = cudaLaunchAttributeProgrammaticStreamSerialization;
    attrs[0].val.programmaticStreamSerializationAllowed = 1;
    cfg.attrs = attrs;
    cfg.numAttrs = 1;
    cudaLaunchKernelEx(&cfg, logits_tc, ctxv, logits_out);
}